// round 7
// baseline (speedup 1.0000x reference)
#include <cuda_runtime.h>
#include <math.h>

#define NQ 19
#define NL 3
#define NA 8
#define NSTATE (1u << NQ)   // 524288 amplitudes, 4 MiB as float2

// Static device scratch (no allocations allowed)
__device__ float2 g_state[NSTATE];
__device__ float2 g_U[NL][NQ][4];   // fused 2x2 complex unitary per layer/wire: [u00,u01,u10,u11]

__device__ __forceinline__ float2 cmul(float2 a, float2 b) {
    return make_float2(a.x * b.x - a.y * b.y, a.x * b.y + a.y * b.x);
}

// ---------------------------------------------------------------------------
// Setup: build fused U = RZ*RY*RX per (layer, wire) (layer 2: RY*RX only,
// since diagonal RZ/CZ don't affect probabilities), zero the output.
// ---------------------------------------------------------------------------
__global__ void setup_kernel(const float* __restrict__ inputs,
                             const float* __restrict__ yw,
                             const float* __restrict__ zw,
                             float* __restrict__ out)
{
    int t = threadIdx.x;
    if (t < NA) out[t] = 0.0f;
    if (t >= NL * NQ) return;
    int l = t / NQ, w = t % NQ;

    const float TWO_PI = 6.28318530717958647692f;
    const float PI_F   = 3.14159265358979323846f;

    float x = inputs[w];
    float a;
    if (w >= NQ - 2) {                       // directional wires 17,18
        a = (x >= 0.5f) ? PI_F : 0.0f;
    } else {                                 // scale [-1.5,1.5] -> [0,2pi], clip
        a = (x + 1.5f) * (TWO_PI / 3.0f);
        a = fminf(fmaxf(a, 0.0f), TWO_PI);
    }

    float sx, cx; sincosf(0.5f * a, &sx, &cx);
    // RX = [[cx, -i sx], [-i sx, cx]]
    float2 rx00 = make_float2(cx, 0.f);
    float2 rx01 = make_float2(0.f, -sx);
    float2 rx10 = make_float2(0.f, -sx);
    float2 rx11 = make_float2(cx, 0.f);

    float y = yw[l * NQ + w];
    float sy, cy; sincosf(0.5f * y, &sy, &cy);
    // M = RY * RX, RY = [[cy,-sy],[sy,cy]]
    float2 m00 = make_float2(cy * rx00.x - sy * rx10.x, cy * rx00.y - sy * rx10.y);
    float2 m01 = make_float2(cy * rx01.x - sy * rx11.x, cy * rx01.y - sy * rx11.y);
    float2 m10 = make_float2(sy * rx00.x + cy * rx10.x, sy * rx00.y + cy * rx10.y);
    float2 m11 = make_float2(sy * rx01.x + cy * rx11.x, sy * rx01.y + cy * rx11.y);

    if (l < NL - 1) {                        // fold RZ for layers 0,1
        float z = zw[l * NQ + w];
        float sz, cz; sincosf(0.5f * z, &sz, &cz);
        float2 e0 = make_float2(cz, -sz);    // e^{-iz/2} (row 0)
        float2 e1 = make_float2(cz,  sz);    // e^{+iz/2} (row 1)
        m00 = cmul(e0, m00); m01 = cmul(e0, m01);
        m10 = cmul(e1, m10); m11 = cmul(e1, m11);
    }
    g_U[l][w][0] = m00; g_U[l][w][1] = m01;
    g_U[l][w][2] = m10; g_U[l][w][3] = m11;
}

// ---------------------------------------------------------------------------
// Pass A: gates on low wires 0..9. Tile = 1024 contiguous amplitudes (8 KB).
// Grid 512 x 256 threads. INIT variant synthesizes |0..0> (no global read).
// ---------------------------------------------------------------------------
template<bool INIT>
__global__ void __launch_bounds__(256) low_kernel(int layer)
{
    __shared__ float sre[1024];
    __shared__ float sim[1024];
    const int tid = threadIdx.x;
    const unsigned base = blockIdx.x * 1024u;

    if (INIT) {
        #pragma unroll
        for (int k = 0; k < 4; k++) { int j = tid + k * 256; sre[j] = 0.f; sim[j] = 0.f; }
        if (tid == 0 && blockIdx.x == 0) sre[0] = 1.f;
    } else {
        #pragma unroll
        for (int k = 0; k < 4; k++) {
            int j = tid + k * 256;
            float2 v = g_state[base + j];
            sre[j] = v.x; sim[j] = v.y;
        }
    }
    __syncthreads();

    #pragma unroll
    for (int q = 0; q < 10; q++) {
        const float2 u00 = g_U[layer][q][0], u01 = g_U[layer][q][1];
        const float2 u10 = g_U[layer][q][2], u11 = g_U[layer][q][3];
        #pragma unroll
        for (int k = 0; k < 2; k++) {
            int p  = tid + k * 256;                               // 512 pairs
            int i0 = ((p >> q) << (q + 1)) | (p & ((1 << q) - 1));
            int i1 = i0 | (1 << q);
            float ar = sre[i0], ai = sim[i0];
            float br = sre[i1], bi = sim[i1];
            sre[i0] = u00.x * ar - u00.y * ai + u01.x * br - u01.y * bi;
            sim[i0] = u00.x * ai + u00.y * ar + u01.x * bi + u01.y * br;
            sre[i1] = u10.x * ar - u10.y * ai + u11.x * br - u11.y * bi;
            sim[i1] = u10.x * ai + u10.y * ar + u11.x * bi + u11.y * br;
        }
        __syncthreads();
    }

    #pragma unroll
    for (int k = 0; k < 4; k++) {
        int j = tid + k * 256;
        g_state[base + j] = make_float2(sre[j], sim[j]);
    }
}

// ---------------------------------------------------------------------------
// Pass B: gates on high wires 10..18. Tile = all 512 high-bit combos x
// 4 consecutive low amps (16 KB smem). Global idx = (high<<10)|(blk<<2)|low.
// Fuses CZ-ring sign (layers 0,1) or the <Z_w> reduction (layer 2).
// ---------------------------------------------------------------------------
template<bool LAST>
__global__ void __launch_bounds__(256) high_kernel(int layer, float* __restrict__ out)
{
    __shared__ float sre[2048];
    __shared__ float sim[2048];
    const int tid = threadIdx.x;
    const unsigned blk = blockIdx.x;   // global bits 2..9

    #pragma unroll
    for (int k = 0; k < 8; k++) {
        int j = tid + k * 256;
        unsigned g = ((unsigned)(j >> 2) << 10) | (blk << 2) | (unsigned)(j & 3);
        float2 v = g_state[g];
        sre[j] = v.x; sim[j] = v.y;
    }
    __syncthreads();

    #pragma unroll
    for (int q = 0; q < 9; q++) {
        const float2 u00 = g_U[layer][10 + q][0], u01 = g_U[layer][10 + q][1];
        const float2 u10 = g_U[layer][10 + q][2], u11 = g_U[layer][10 + q][3];
        #pragma unroll
        for (int k = 0; k < 4; k++) {
            int p   = tid + k * 256;                              // 1024 pairs
            int low = p & 3;
            int hp  = p >> 2;                                     // [0,256)
            int h0  = ((hp >> q) << (q + 1)) | (hp & ((1 << q) - 1));
            int i0  = (h0 << 2) | low;
            int i1  = i0 | (4 << q);
            float ar = sre[i0], ai = sim[i0];
            float br = sre[i1], bi = sim[i1];
            sre[i0] = u00.x * ar - u00.y * ai + u01.x * br - u01.y * bi;
            sim[i0] = u00.x * ai + u00.y * ar + u01.x * bi + u01.y * br;
            sre[i1] = u10.x * ar - u10.y * ai + u11.x * br - u11.y * bi;
            sim[i1] = u10.x * ai + u10.y * ar + u11.x * bi + u11.y * br;
        }
        __syncthreads();
    }

    if (!LAST) {
        // CZ ring: sign = (-1)^[ popc((g & g>>1) & 0x3FFFF) + (bit0 & bit18) ]
        #pragma unroll
        for (int k = 0; k < 8; k++) {
            int j = tid + k * 256;
            unsigned g = ((unsigned)(j >> 2) << 10) | (blk << 2) | (unsigned)(j & 3);
            unsigned par = __popc((g & (g >> 1)) & 0x3FFFFu) + ((g & (g >> 18)) & 1u);
            float s = (par & 1u) ? -1.f : 1.f;
            g_state[g] = make_float2(s * sre[j], s * sim[j]);
        }
    } else {
        // <Z_w> = sum p * (1-2*bit_w). bits 0,1 vary inside the 4-group;
        // bits 2..7 are constant per block (from blk).
        float S = 0.f, S0 = 0.f, S1 = 0.f;
        #pragma unroll
        for (int k = 0; k < 8; k++) {
            int j = tid + k * 256;
            float p = sre[j] * sre[j] + sim[j] * sim[j];
            S  += p;
            S0 += (j & 1) ? -p : p;
            S1 += (j & 2) ? -p : p;
        }
        #pragma unroll
        for (int o = 16; o > 0; o >>= 1) {
            S  += __shfl_xor_sync(0xFFFFFFFFu, S,  o);
            S0 += __shfl_xor_sync(0xFFFFFFFFu, S0, o);
            S1 += __shfl_xor_sync(0xFFFFFFFFu, S1, o);
        }
        __syncthreads();                 // done reading sre/sim before reuse
        if ((tid & 31) == 0) {
            int wi = tid >> 5;           // 8 warps
            sre[wi]      = S;
            sre[8 + wi]  = S0;
            sre[16 + wi] = S1;
        }
        __syncthreads();
        if (tid == 0) {
            float St = 0.f, S0t = 0.f, S1t = 0.f;
            #pragma unroll
            for (int i = 0; i < 8; i++) { St += sre[i]; S0t += sre[8 + i]; S1t += sre[16 + i]; }
            atomicAdd(out + 0, S0t);
            atomicAdd(out + 1, S1t);
            #pragma unroll
            for (int w = 2; w < 8; w++) {
                float sgn = ((blk >> (w - 2)) & 1u) ? -1.f : 1.f;
                atomicAdd(out + w, sgn * St);
            }
        }
    }
}

extern "C" void kernel_launch(void* const* d_in, const int* in_sizes, int n_in,
                              void* d_out, int out_size)
{
    (void)in_sizes; (void)n_in; (void)out_size;
    const float* inputs = (const float*)d_in[0];
    const float* yw     = (const float*)d_in[1];
    const float* zw     = (const float*)d_in[2];
    float* out = (float*)d_out;

    setup_kernel<<<1, 64>>>(inputs, yw, zw, out);
    low_kernel<true ><<<512, 256>>>(0);
    high_kernel<false><<<256, 256>>>(0, out);
    low_kernel<false><<<512, 256>>>(1);
    high_kernel<false><<<256, 256>>>(1, out);
    low_kernel<false><<<512, 256>>>(2);
    high_kernel<true ><<<256, 256>>>(2, out);
}

// round 8
// speedup vs baseline: 1.9005x; 1.9005x over previous
#include <cuda_runtime.h>
#include <math.h>

#define NQ 19
#define NL 3
#define NA 8
#define NSTATE (1u << NQ)   // 524288 amplitudes, 4 MiB as float2

__device__ float2 g_state[NSTATE];

__device__ __forceinline__ float2 cmul(float2 a, float2 b) {
    return make_float2(a.x * b.x - a.y * b.y, a.x * b.y + a.y * b.x);
}

// ---------------------------------------------------------------------------
// Build this layer's fused 2x2 unitaries U = (RZ)*RY*RX into smem.
// Layer NL-1 omits RZ (diagonal; cannot change probabilities).
// All threads must call (has __syncthreads).
// ---------------------------------------------------------------------------
template<int LAYER>
__device__ __forceinline__ void build_U(float2 (*sU)[4],
                                        const float* __restrict__ inputs,
                                        const float* __restrict__ yw,
                                        const float* __restrict__ zw)
{
    int w = threadIdx.x;
    if (w < NQ) {
        const float TWO_PI = 6.28318530717958647692f;
        const float PI_F   = 3.14159265358979323846f;

        float x = inputs[w];
        float a;
        if (w >= NQ - 2) {                       // directional wires
            a = (x >= 0.5f) ? PI_F : 0.0f;
        } else {                                 // [-1.5,1.5] -> [0,2pi], clip
            a = (x + 1.5f) * (TWO_PI / 3.0f);
            a = fminf(fmaxf(a, 0.0f), TWO_PI);
        }

        float sx, cx; sincosf(0.5f * a, &sx, &cx);
        float y = yw[LAYER * NQ + w];
        float sy, cy; sincosf(0.5f * y, &sy, &cy);

        // M = RY * RX;  RX = [[cx,-i sx],[-i sx,cx]], RY = [[cy,-sy],[sy,cy]]
        float2 m00 = make_float2(cy * cx, sy * sx);
        float2 m01 = make_float2(-sy * cx, -cy * sx);
        float2 m10 = make_float2(sy * cx, -cy * sx);
        float2 m11 = make_float2(cy * cx, -sy * sx);

        if (LAYER < NL - 1) {                    // fold RZ
            float z = zw[LAYER * NQ + w];
            float sz, cz; sincosf(0.5f * z, &sz, &cz);
            float2 e0 = make_float2(cz, -sz);
            float2 e1 = make_float2(cz,  sz);
            m00 = cmul(e0, m00); m01 = cmul(e0, m01);
            m10 = cmul(e1, m10); m11 = cmul(e1, m11);
        }
        sU[w][0] = m00; sU[w][1] = m01;
        sU[w][2] = m10; sU[w][3] = m11;
    }
    __syncthreads();
}

// Gate on a register bit (MB in {1,2,4}) of the 8-amp register file.
template<int MB>
__device__ __forceinline__ void gate_reg(float vr[8], float vi[8], const float2* u)
{
    float2 u00 = u[0], u01 = u[1], u10 = u[2], u11 = u[3];
    #pragma unroll
    for (int r0 = 0; r0 < 8; r0++) {
        if (r0 & MB) continue;
        int r1 = r0 | MB;
        float ar = vr[r0], ai = vi[r0], br = vr[r1], bi = vi[r1];
        vr[r0] = u00.x * ar - u00.y * ai + u01.x * br - u01.y * bi;
        vi[r0] = u00.x * ai + u00.y * ar + u01.x * bi + u01.y * br;
        vr[r1] = u10.x * ar - u10.y * ai + u11.x * br - u11.y * bi;
        vi[r1] = u10.x * ai + u10.y * ar + u11.x * bi + u11.y * br;
    }
}

// Gate on a lane bit (mask M) via warp shuffles.
template<int M>
__device__ __forceinline__ void gate_lane(float vr[8], float vi[8],
                                          unsigned lane, const float2* u)
{
    bool hi = (lane & M) != 0;
    float2 A = hi ? u[3] : u[0];   // coefficient of own amp
    float2 B = hi ? u[2] : u[1];   // coefficient of partner amp
    #pragma unroll
    for (int r = 0; r < 8; r++) {
        float wr = __shfl_xor_sync(0xFFFFFFFFu, vr[r], M);
        float wi = __shfl_xor_sync(0xFFFFFFFFu, vi[r], M);
        float ar = vr[r], ai = vi[r];
        vr[r] = A.x * ar - A.y * ai + B.x * wr - B.y * wi;
        vi[r] = A.x * ai + A.y * ar + B.x * wi + B.y * wr;
    }
}

__device__ __forceinline__ float cz_sign(unsigned g)
{
    unsigned par = __popc((g & (g >> 1)) & 0x3FFFFu) + ((g & (g >> 18)) & 1u);
    return (par & 1u) ? -1.0f : 1.0f;
}

// ---------------------------------------------------------------------------
// Layer 0: after all single-qubit gates the state is a product state:
// amp[g] = prod_w U0[w][bit_w(g), 0]. Write it directly with the layer-0 CZ
// sign fused. g = blk*1024 + k*256 + tid (fully coalesced). No read.
// Also zeroes out[] (atomics accumulate in the last pass).
// ---------------------------------------------------------------------------
__global__ void __launch_bounds__(256) init_kernel(const float* __restrict__ inputs,
                                                   const float* __restrict__ yw,
                                                   const float* __restrict__ zw,
                                                   float* __restrict__ out)
{
    __shared__ float2 sU[NQ][4];
    build_U<0>(sU, inputs, yw, zw);

    const unsigned tid = threadIdx.x;
    const unsigned blk = blockIdx.x;
    if (blk == 0 && tid < NA) out[tid] = 0.0f;

    // fixed factors: wires 0..7 from tid bits, wires 10..18 from blk bits
    float2 P = sU[0][(tid & 1u) ? 2 : 0];
    #pragma unroll
    for (int w = 1; w < 8; w++)
        P = cmul(P, sU[w][((tid >> w) & 1u) ? 2 : 0]);
    #pragma unroll
    for (int w = 10; w < NQ; w++)
        P = cmul(P, sU[w][((blk >> (w - 10)) & 1u) ? 2 : 0]);

    float2 f8a = sU[8][0], f8b = sU[8][2];
    float2 f9a = sU[9][0], f9b = sU[9][2];
    float2 q[4];
    q[0] = cmul(f8a, f9a); q[1] = cmul(f8b, f9a);
    q[2] = cmul(f8a, f9b); q[3] = cmul(f8b, f9b);

    #pragma unroll
    for (int k = 0; k < 4; k++) {
        unsigned g = blk * 1024u + k * 256u + tid;
        float2 amp = cmul(P, q[k]);
        float s = cz_sign(g);
        g_state[g] = make_float2(s * amp.x, s * amp.y);
    }
}

// ---------------------------------------------------------------------------
// Low pass: wires 0..10. Tile = 2048 contiguous amps, 256 thr, 8 amps/thread.
// Local bit layout L1: lane=t[4:0], warp=t[7:5], reg=t[10:8].
// Gates: reg {8,9,10}, shfl {0..4}, one smem transpose, reg {5,6,7}.
// ---------------------------------------------------------------------------
template<int LAYER>
__global__ void __launch_bounds__(256) lowpass_kernel(const float* __restrict__ inputs,
                                                      const float* __restrict__ yw,
                                                      const float* __restrict__ zw)
{
    __shared__ float2 sU[NQ][4];
    __shared__ float2 sx[2048];
    build_U<LAYER>(sU, inputs, yw, zw);

    const unsigned tid  = threadIdx.x;
    const unsigned lane = tid & 31u;
    const unsigned base = blockIdx.x << 11;

    float vr[8], vi[8];
    #pragma unroll
    for (int r = 0; r < 8; r++) {
        float2 a = g_state[base + r * 256u + tid];
        vr[r] = a.x; vi[r] = a.y;
    }

    gate_reg<1>(vr, vi, sU[8]);
    gate_reg<2>(vr, vi, sU[9]);
    gate_reg<4>(vr, vi, sU[10]);

    gate_lane<1 >(vr, vi, lane, sU[0]);
    gate_lane<2 >(vr, vi, lane, sU[1]);
    gate_lane<4 >(vr, vi, lane, sU[2]);
    gate_lane<8 >(vr, vi, lane, sU[3]);
    gate_lane<16>(vr, vi, lane, sU[4]);

    // transpose: move warp bits t[7:5] into registers
    #pragma unroll
    for (int r = 0; r < 8; r++) sx[r * 256u + tid] = make_float2(vr[r], vi[r]);
    __syncthreads();
    const unsigned b2 = ((tid >> 5) << 8) | lane;   // t with t[7:5]=r slot
    #pragma unroll
    for (int r = 0; r < 8; r++) {
        float2 a = sx[b2 + r * 32u];
        vr[r] = a.x; vi[r] = a.y;
    }

    gate_reg<1>(vr, vi, sU[5]);
    gate_reg<2>(vr, vi, sU[6]);
    gate_reg<4>(vr, vi, sU[7]);

    #pragma unroll
    for (int r = 0; r < 8; r++)
        g_state[base + b2 + r * 32u] = make_float2(vr[r], vi[r]);
}

// ---------------------------------------------------------------------------
// High pass: wires 11..18 (+3 low pad bits for coalescing).
// Local t[10:0]: t[2:0]=g[2:0], t[10:3]=g[18:11]; block = g[10:3].
// L1: lane=t[4:0] (wires -,-,-,11,12), warp=t[7:5] (13,14,15), reg=t[10:8]
// (16,17,18). Fuses CZ sign (LAST=false) or the <Z_w> reduction (LAST=true).
// ---------------------------------------------------------------------------
template<int LAYER, bool LAST>
__global__ void __launch_bounds__(256) highpass_kernel(const float* __restrict__ inputs,
                                                       const float* __restrict__ yw,
                                                       const float* __restrict__ zw,
                                                       float* __restrict__ out)
{
    __shared__ float2 sU[NQ][4];
    __shared__ float2 sx[2048];
    build_U<LAYER>(sU, inputs, yw, zw);

    const unsigned tid  = threadIdx.x;
    const unsigned lane = tid & 31u;
    const unsigned blk  = blockIdx.x;

    float vr[8], vi[8];
    #pragma unroll
    for (int r = 0; r < 8; r++) {
        unsigned t = r * 256u + tid;
        unsigned g = ((t >> 3) << 11) | (blk << 3) | (t & 7u);
        float2 a = g_state[g];
        vr[r] = a.x; vi[r] = a.y;
    }

    gate_reg<1>(vr, vi, sU[16]);
    gate_reg<2>(vr, vi, sU[17]);
    gate_reg<4>(vr, vi, sU[18]);

    gate_lane<8 >(vr, vi, lane, sU[11]);
    gate_lane<16>(vr, vi, lane, sU[12]);

    #pragma unroll
    for (int r = 0; r < 8; r++) sx[r * 256u + tid] = make_float2(vr[r], vi[r]);
    __syncthreads();
    const unsigned b2 = ((tid >> 5) << 8) | lane;
    #pragma unroll
    for (int r = 0; r < 8; r++) {
        float2 a = sx[b2 + r * 32u];
        vr[r] = a.x; vi[r] = a.y;
    }

    gate_reg<1>(vr, vi, sU[13]);
    gate_reg<2>(vr, vi, sU[14]);
    gate_reg<4>(vr, vi, sU[15]);

    if (!LAST) {
        #pragma unroll
        for (int r = 0; r < 8; r++) {
            unsigned t = b2 + r * 32u;
            unsigned g = ((t >> 3) << 11) | (blk << 3) | (t & 7u);
            float s = cz_sign(g);
            g_state[g] = make_float2(s * vr[r], s * vi[r]);
        }
    } else {
        // <Z_w>: wires 0,1,2 sign from lane bits (t[2:0]=lane[2:0], constant
        // across this thread's 8 regs); wires 3..7 sign from blk bits 0..4.
        float P = 0.0f;
        #pragma unroll
        for (int r = 0; r < 8; r++) P += vr[r] * vr[r] + vi[r] * vi[r];
        float s0 = (lane & 1u) ? -P : P;
        float s1 = (lane & 2u) ? -P : P;
        float s2 = (lane & 4u) ? -P : P;
        #pragma unroll
        for (int o = 16; o > 0; o >>= 1) {
            P  += __shfl_xor_sync(0xFFFFFFFFu, P,  o);
            s0 += __shfl_xor_sync(0xFFFFFFFFu, s0, o);
            s1 += __shfl_xor_sync(0xFFFFFFFFu, s1, o);
            s2 += __shfl_xor_sync(0xFFFFFFFFu, s2, o);
        }
        __syncthreads();                 // done with sx; reuse for reduction
        float* sf = (float*)sx;
        if (lane == 0) {
            unsigned wi = tid >> 5;      // 8 warps
            sf[wi]      = P;
            sf[8 + wi]  = s0;
            sf[16 + wi] = s1;
            sf[24 + wi] = s2;
        }
        __syncthreads();
        if (tid == 0) {
            float Pt = 0.f, S0 = 0.f, S1 = 0.f, S2 = 0.f;
            #pragma unroll
            for (int i = 0; i < 8; i++) {
                Pt += sf[i]; S0 += sf[8 + i]; S1 += sf[16 + i]; S2 += sf[24 + i];
            }
            atomicAdd(out + 0, S0);
            atomicAdd(out + 1, S1);
            atomicAdd(out + 2, S2);
            #pragma unroll
            for (int w = 3; w < 8; w++) {
                float sgn = ((blk >> (w - 3)) & 1u) ? -1.f : 1.f;
                atomicAdd(out + w, sgn * Pt);
            }
        }
    }
}

extern "C" void kernel_launch(void* const* d_in, const int* in_sizes, int n_in,
                              void* d_out, int out_size)
{
    (void)in_sizes; (void)n_in; (void)out_size;
    const float* inputs = (const float*)d_in[0];
    const float* yw     = (const float*)d_in[1];
    const float* zw     = (const float*)d_in[2];
    float* out = (float*)d_out;

    init_kernel<<<512, 256>>>(inputs, yw, zw, out);          // layer 0 (+CZ)
    lowpass_kernel<1><<<256, 256>>>(inputs, yw, zw);         // layer 1 wires 0-10
    highpass_kernel<1, false><<<256, 256>>>(inputs, yw, zw, out); // 11-18 +CZ
    lowpass_kernel<2><<<256, 256>>>(inputs, yw, zw);         // layer 2 wires 0-10
    highpass_kernel<2, true ><<<256, 256>>>(inputs, yw, zw, out); // 11-18 +reduce
}

// round 9
// speedup vs baseline: 1.9437x; 1.0228x over previous
#include <cuda_runtime.h>
#include <math.h>

#define NQ 19
#define NL 3
#define NA 8
#define NSTATE (1u << NQ)   // 524288 amplitudes, 4 MiB as float2

__device__ float2 g_state[NSTATE];

__device__ __forceinline__ float2 cmul(float2 a, float2 b) {
    return make_float2(a.x * b.x - a.y * b.y, a.x * b.y + a.y * b.x);
}

// ---------------------------------------------------------------------------
// Build one layer's fused 2x2 unitaries U = (RZ)*RY*RX into smem.
// Layer NL-1 omits RZ (diagonal; cannot change probabilities).
// All threads must call (contains __syncthreads).
// ---------------------------------------------------------------------------
template<int LAYER>
__device__ __forceinline__ void build_U(float2 (*sU)[4],
                                        const float* __restrict__ inputs,
                                        const float* __restrict__ yw,
                                        const float* __restrict__ zw)
{
    int w = threadIdx.x;
    if (w < NQ) {
        const float TWO_PI = 6.28318530717958647692f;
        const float PI_F   = 3.14159265358979323846f;

        float x = inputs[w];
        float a;
        if (w >= NQ - 2) {                       // directional wires
            a = (x >= 0.5f) ? PI_F : 0.0f;
        } else {                                 // [-1.5,1.5] -> [0,2pi], clip
            a = (x + 1.5f) * (TWO_PI / 3.0f);
            a = fminf(fmaxf(a, 0.0f), TWO_PI);
        }

        float sx, cx; sincosf(0.5f * a, &sx, &cx);
        float y = yw[LAYER * NQ + w];
        float sy, cy; sincosf(0.5f * y, &sy, &cy);

        // M = RY*RX; RX = [[cx,-i sx],[-i sx,cx]], RY = [[cy,-sy],[sy,cy]]
        float2 m00 = make_float2(cy * cx, sy * sx);
        float2 m01 = make_float2(-sy * cx, -cy * sx);
        float2 m10 = make_float2(sy * cx, -cy * sx);
        float2 m11 = make_float2(cy * cx, -sy * sx);

        if (LAYER < NL - 1) {                    // fold RZ
            float z = zw[LAYER * NQ + w];
            float sz, cz; sincosf(0.5f * z, &sz, &cz);
            float2 e0 = make_float2(cz, -sz);
            float2 e1 = make_float2(cz,  sz);
            m00 = cmul(e0, m00); m01 = cmul(e0, m01);
            m10 = cmul(e1, m10); m11 = cmul(e1, m11);
        }
        sU[w][0] = m00; sU[w][1] = m01;
        sU[w][2] = m10; sU[w][3] = m11;
    }
    __syncthreads();
}

// Gate on a register bit (MB in {1,2}) of the 4-amp register file.
template<int MB>
__device__ __forceinline__ void gate_reg(float vr[4], float vi[4], const float2* u)
{
    float2 u00 = u[0], u01 = u[1], u10 = u[2], u11 = u[3];
    #pragma unroll
    for (int r0 = 0; r0 < 4; r0++) {
        if (r0 & MB) continue;
        int r1 = r0 | MB;
        float ar = vr[r0], ai = vi[r0], br = vr[r1], bi = vi[r1];
        vr[r0] = u00.x * ar - u00.y * ai + u01.x * br - u01.y * bi;
        vi[r0] = u00.x * ai + u00.y * ar + u01.x * bi + u01.y * br;
        vr[r1] = u10.x * ar - u10.y * ai + u11.x * br - u11.y * bi;
        vi[r1] = u10.x * ai + u10.y * ar + u11.x * bi + u11.y * br;
    }
}

// Gate on a lane bit (mask M) via warp shuffles.
template<int M>
__device__ __forceinline__ void gate_lane(float vr[4], float vi[4],
                                          unsigned lane, const float2* u)
{
    bool hi = (lane & M) != 0;
    float2 A = hi ? u[3] : u[0];   // coefficient of own amp
    float2 B = hi ? u[2] : u[1];   // coefficient of partner amp
    #pragma unroll
    for (int r = 0; r < 4; r++) {
        float wr = __shfl_xor_sync(0xFFFFFFFFu, vr[r], M);
        float wi = __shfl_xor_sync(0xFFFFFFFFu, vi[r], M);
        float ar = vr[r], ai = vi[r];
        vr[r] = A.x * ar - A.y * ai + B.x * wr - B.y * wi;
        vi[r] = A.x * ai + A.y * ar + B.x * wi + B.y * wr;
    }
}

__device__ __forceinline__ float cz_sign(unsigned g)
{
    unsigned par = __popc((g & (g >> 1)) & 0x3FFFFu) + ((g & (g >> 18)) & 1u);
    return (par & 1u) ? -1.0f : 1.0f;
}

// Bank swizzle: s[3]=a[3]^a[7], s[4]=a[4]^a[8] -> both transpose phases are
// 32-bank conflict-free for the layouts below.
__device__ __forceinline__ unsigned swz(unsigned a) { return a ^ ((a >> 4) & 0x18u); }

// Phase-2 local amp index for (tid, reg r'):
// a[7]=t0 a[8]=t1 a[0]=t2 a[1]=t3 a[2]=t4 a[3]=t5 a[4]=t6 a[9]=t7 a[10]=t8, a[6:5]=r'
__device__ __forceinline__ unsigned phase2_a(unsigned t, unsigned r)
{
    return ((t >> 2) & 7u)            // a[2:0]
         | (((t >> 5) & 3u) << 3)     // a[4:3]
         | (r << 5)                   // a[6:5]
         | ((t & 3u) << 7)            // a[8:7]
         | (((t >> 7) & 3u) << 9);    // a[10:9]
}

// ---------------------------------------------------------------------------
// Shared gate core for the low pass (wires 0..10 on local bits a[10:0]).
// Phase 1 layout: a = (r<<9)|t  (lane=a[4:0], warp=a[8:5], reg=a[10:9]).
// Gates: lane {0..4}, reg {9,10}; transpose; reg {5,6}, lane {7(m1), 8(m2)}.
// On exit registers hold amps at phase2_a(t, r); caller stores.
// ---------------------------------------------------------------------------
__device__ __forceinline__ void low_gates(float vr[4], float vi[4],
                                          float2 (*sU)[4],
                                          float* sre, float* sim,
                                          unsigned tid, unsigned lane)
{
    gate_reg<1>(vr, vi, sU[9]);
    gate_reg<2>(vr, vi, sU[10]);
    gate_lane<1 >(vr, vi, lane, sU[0]);
    gate_lane<2 >(vr, vi, lane, sU[1]);
    gate_lane<4 >(vr, vi, lane, sU[2]);
    gate_lane<8 >(vr, vi, lane, sU[3]);
    gate_lane<16>(vr, vi, lane, sU[4]);

    #pragma unroll
    for (int r = 0; r < 4; r++) {
        unsigned s = swz((unsigned)(r << 9) | tid);
        sre[s] = vr[r]; sim[s] = vi[r];
    }
    __syncthreads();
    #pragma unroll
    for (int r = 0; r < 4; r++) {
        unsigned s = swz(phase2_a(tid, r));
        vr[r] = sre[s]; vi[r] = sim[s];
    }

    gate_reg<1>(vr, vi, sU[5]);
    gate_reg<2>(vr, vi, sU[6]);
    gate_lane<1>(vr, vi, lane, sU[7]);
    gate_lane<2>(vr, vi, lane, sU[8]);
}

// ---------------------------------------------------------------------------
// Kernel 1: layer-0 product state (all 19 single-qubit gates analytic) with
// layer-0 CZ sign fused, then layer-1 low-pass gates. Write-only to global.
// ---------------------------------------------------------------------------
__global__ void __launch_bounds__(512) init_low_kernel(const float* __restrict__ inputs,
                                                       const float* __restrict__ yw,
                                                       const float* __restrict__ zw,
                                                       float* __restrict__ out)
{
    __shared__ float2 sU0[NQ][4];
    __shared__ float2 sU1[NQ][4];
    __shared__ float sre[2048];
    __shared__ float sim[2048];
    build_U<0>(sU0, inputs, yw, zw);
    build_U<1>(sU1, inputs, yw, zw);

    const unsigned tid  = threadIdx.x;
    const unsigned lane = tid & 31u;
    const unsigned blk  = blockIdx.x;
    const unsigned base = blk << 11;
    if (blk == 0 && tid < NA) out[tid] = 0.0f;

    // product-state factor common to this thread: wires 0..8 (tid bits) and
    // wires 11..18 (blk bits)
    float2 Pc = sU0[0][(tid & 1u) ? 2 : 0];
    #pragma unroll
    for (int w = 1; w < 9; w++)
        Pc = cmul(Pc, sU0[w][((tid >> w) & 1u) ? 2 : 0]);
    #pragma unroll
    for (int w = 11; w < NQ; w++)
        Pc = cmul(Pc, sU0[w][((blk >> (w - 11)) & 1u) ? 2 : 0]);

    float vr[4], vi[4];
    #pragma unroll
    for (int r = 0; r < 4; r++) {
        float2 q = cmul(sU0[9][(r & 1) ? 2 : 0], sU0[10][(r & 2) ? 2 : 0]);
        float2 amp = cmul(Pc, q);
        unsigned g = base | (unsigned)(r << 9) | tid;
        float s = cz_sign(g);
        vr[r] = s * amp.x; vi[r] = s * amp.y;
    }

    low_gates(vr, vi, sU1, sre, sim, tid, lane);

    #pragma unroll
    for (int r = 0; r < 4; r++)
        g_state[base | phase2_a(tid, r)] = make_float2(vr[r], vi[r]);
}

// ---------------------------------------------------------------------------
// Kernel 3: layer-2 low pass (read-modify-write).
// ---------------------------------------------------------------------------
__global__ void __launch_bounds__(512) low2_kernel(const float* __restrict__ inputs,
                                                   const float* __restrict__ yw,
                                                   const float* __restrict__ zw)
{
    __shared__ float2 sU[NQ][4];
    __shared__ float sre[2048];
    __shared__ float sim[2048];
    build_U<2>(sU, inputs, yw, zw);

    const unsigned tid  = threadIdx.x;
    const unsigned lane = tid & 31u;
    const unsigned base = blockIdx.x << 11;

    float vr[4], vi[4];
    #pragma unroll
    for (int r = 0; r < 4; r++) {
        float2 a = g_state[base | (unsigned)(r << 9) | tid];
        vr[r] = a.x; vi[r] = a.y;
    }

    low_gates(vr, vi, sU, sre, sim, tid, lane);

    #pragma unroll
    for (int r = 0; r < 4; r++)
        g_state[base | phase2_a(tid, r)] = make_float2(vr[r], vi[r]);
}

// ---------------------------------------------------------------------------
// High pass: wires 11..18 on local bits a[10:3]; a[2:0] = g[2:0] pad.
// g = (a[10:3]<<11) | (blk<<3) | a[2:0].
// Phase 1: lane gates a[3](w11,m8), a[4](w12,m16); reg a[9](w17), a[10](w18).
// Transpose; reg a[5](w13), a[6](w14); lane a[7](w15,m1), a[8](w16,m2).
// LAST=false: fused CZ sign writeback (layer 1).
// LAST=true : fused <Z_w> reduction (layer 2; RZ/CZ dropped as diagonal).
// ---------------------------------------------------------------------------
template<int LAYER, bool LAST>
__global__ void __launch_bounds__(512) highpass_kernel(const float* __restrict__ inputs,
                                                       const float* __restrict__ yw,
                                                       const float* __restrict__ zw,
                                                       float* __restrict__ out)
{
    __shared__ float2 sU[NQ][4];
    __shared__ float sre[2048];
    __shared__ float sim[2048];
    build_U<LAYER>(sU, inputs, yw, zw);

    const unsigned tid  = threadIdx.x;
    const unsigned lane = tid & 31u;
    const unsigned blk  = blockIdx.x;

    float vr[4], vi[4];
    #pragma unroll
    for (int r = 0; r < 4; r++) {
        unsigned a = (unsigned)(r << 9) | tid;
        unsigned g = ((a >> 3) << 11) | (blk << 3) | (a & 7u);
        float2 v = g_state[g];
        vr[r] = v.x; vi[r] = v.y;
    }

    gate_reg<1>(vr, vi, sU[17]);
    gate_reg<2>(vr, vi, sU[18]);
    gate_lane<8 >(vr, vi, lane, sU[11]);
    gate_lane<16>(vr, vi, lane, sU[12]);

    #pragma unroll
    for (int r = 0; r < 4; r++) {
        unsigned s = swz((unsigned)(r << 9) | tid);
        sre[s] = vr[r]; sim[s] = vi[r];
    }
    __syncthreads();
    #pragma unroll
    for (int r = 0; r < 4; r++) {
        unsigned s = swz(phase2_a(tid, r));
        vr[r] = sre[s]; vi[r] = sim[s];
    }

    gate_reg<1>(vr, vi, sU[13]);
    gate_reg<2>(vr, vi, sU[14]);
    gate_lane<1>(vr, vi, lane, sU[15]);
    gate_lane<2>(vr, vi, lane, sU[16]);

    if (!LAST) {
        #pragma unroll
        for (int r = 0; r < 4; r++) {
            unsigned a = phase2_a(tid, r);
            unsigned g = ((a >> 3) << 11) | (blk << 3) | (a & 7u);
            float s = cz_sign(g);
            g_state[g] = make_float2(s * vr[r], s * vi[r]);
        }
    } else {
        // amps of this thread share a[2:0] = tid[4:2] = g[2:0] -> wires 0,1,2
        float P = 0.0f;
        #pragma unroll
        for (int r = 0; r < 4; r++) P += vr[r] * vr[r] + vi[r] * vi[r];
        float s0 = (tid & 4u)  ? -P : P;   // g[0]
        float s1 = (tid & 8u)  ? -P : P;   // g[1]
        float s2 = (tid & 16u) ? -P : P;   // g[2]
        #pragma unroll
        for (int o = 16; o > 0; o >>= 1) {
            P  += __shfl_xor_sync(0xFFFFFFFFu, P,  o);
            s0 += __shfl_xor_sync(0xFFFFFFFFu, s0, o);
            s1 += __shfl_xor_sync(0xFFFFFFFFu, s1, o);
            s2 += __shfl_xor_sync(0xFFFFFFFFu, s2, o);
        }
        __syncthreads();                 // done with sre/sim; reuse for staging
        if (lane == 0) {
            unsigned wi = tid >> 5;      // 16 warps
            sre[wi]      = P;
            sre[16 + wi] = s0;
            sre[32 + wi] = s1;
            sre[48 + wi] = s2;
        }
        __syncthreads();
        if (tid == 0) {
            float Pt = 0.f, S0 = 0.f, S1 = 0.f, S2 = 0.f;
            #pragma unroll
            for (int i = 0; i < 16; i++) {
                Pt += sre[i]; S0 += sre[16 + i]; S1 += sre[32 + i]; S2 += sre[48 + i];
            }
            atomicAdd(out + 0, S0);
            atomicAdd(out + 1, S1);
            atomicAdd(out + 2, S2);
            #pragma unroll
            for (int w = 3; w < 8; w++) {   // g[7:3] = blk[4:0]
                float sgn = ((blk >> (w - 3)) & 1u) ? -1.f : 1.f;
                atomicAdd(out + w, sgn * Pt);
            }
        }
    }
}

extern "C" void kernel_launch(void* const* d_in, const int* in_sizes, int n_in,
                              void* d_out, int out_size)
{
    (void)in_sizes; (void)n_in; (void)out_size;
    const float* inputs = (const float*)d_in[0];
    const float* yw     = (const float*)d_in[1];
    const float* zw     = (const float*)d_in[2];
    float* out = (float*)d_out;

    init_low_kernel<<<256, 512>>>(inputs, yw, zw, out);            // L0 + L1 low
    highpass_kernel<1, false><<<256, 512>>>(inputs, yw, zw, out);  // L1 high + CZ
    low2_kernel<<<256, 512>>>(inputs, yw, zw);                     // L2 low
    highpass_kernel<2, true ><<<256, 512>>>(inputs, yw, zw, out);  // L2 high + reduce
}